// round 3
// baseline (speedup 1.0000x reference)
#include <cuda_runtime.h>

#define WARPS 8
#define THREADS 256
#define NSTEP 10
#define XSTRIDE 48   // floats per padded row; 48 % 32 == 16 -> conflict-free LDS.64

typedef unsigned long long u64;

// ---- f32x2 / FSET helpers (sm_103a packed fp32 path, PTX-only) ----
__device__ __forceinline__ float setgt1(float a) {
    float r;
    asm("set.gt.f32.f32 %0, %1, %2;" : "=f"(r) : "f"(a), "f"(1.0f));
    return r;
}
__device__ __forceinline__ u64 fma2(u64 a, u64 b, u64 c) {
    u64 d;
    asm("fma.rn.f32x2 %0, %1, %2, %3;" : "=l"(d) : "l"(a), "l"(b), "l"(c));
    return d;
}
__device__ __forceinline__ u64 pack2(float lo, float hi) {
    u64 d;
    asm("mov.b64 %0, {%1, %2};" : "=l"(d) : "f"(lo), "f"(hi));
    return d;
}
__device__ __forceinline__ void unpack2(u64 v, float& lo, float& hi) {
    asm("mov.b64 {%0, %1}, %2;" : "=f"(lo), "=f"(hi) : "l"(v));
}

// One warp per sample, 1024 element-pairs per sample, 32 pairs per lane.
// TWO independent pair-streams per lane run concurrently (X=rr even, Y=rr
// odd) so the two serial membrane-recurrence chains hide each other's
// latency. Per-t accumulation order is X-then-Y = rr0,rr1,rr2,rr3 --
// bit-identical to the single-stream version.
__global__ void __launch_bounds__(THREADS, 2)
snn_kernel(const float* __restrict__ x, const float* __restrict__ convw,
           const float* __restrict__ convb, const float* __restrict__ fcw,
           const float* __restrict__ fcb, float* __restrict__ out, int nB)
{
    __shared__ __align__(16) float sx[WARPS][18 * XSTRIDE];
    __shared__ __align__(16) float sw0[2048];
    __shared__ __align__(16) float sw1[2048];
    __shared__ float scw[72];
    __shared__ float scb[8];

    const int tid  = threadIdx.x;
    const int warp = tid >> 5;
    const int lane = tid & 31;
    const long long b = (long long)blockIdx.x * WARPS + warp;

    for (int i = tid; i < 2048; i += THREADS) {
        sw0[i] = fcw[i];
        sw1[i] = fcw[2048 + i];
    }
    if (tid < 72) scw[tid] = convw[tid];
    if (tid < 8)  scb[tid] = convb[tid];

    float* sxw = sx[warp];
    #pragma unroll
    for (int i = lane; i < 18 * XSTRIDE; i += 32) sxw[i] = 0.0f;
    __syncwarp();

    if (b < nB) {
        const float4* xb = (const float4*)(x + b * 256);
        #pragma unroll
        for (int i = lane; i < 64; i += 32) {
            float4 v = xb[i];
            int p = i * 4;
            int y = p >> 4, xx = p & 15;
            float* d = &sxw[(y + 1) * XSTRIDE + xx + 1];
            d[0] = v.x; d[1] = v.y; d[2] = v.z; d[3] = v.w;
        }
    }
    __syncthreads();

    if (b < nB) {
        u64 A0[NSTEP], A1[NSTEP];
        #pragma unroll
        for (int t = 0; t < NSTEP; t++) { A0[t] = 0ull; A1[t] = 0ull; }

        const u64 BETA2  = 0x3F6666663F666666ull; // (0.9f, 0.9f)
        const u64 NEG1_2 = 0xBF800000BF800000ull; // (-1.f, -1.f)

        #pragma unroll 1
        for (int ch = 0; ch < 8; ch++) {
            u64 wp[9];
            #pragma unroll
            for (int k = 0; k < 9; k++) {
                float w = scw[ch * 9 + k];
                wp[k] = pack2(w, w);
            }
            const float cbias = scb[ch];
            const u64 bias2 = pack2(cbias, cbias);

            #pragma unroll 1
            for (int g = 0; g < 2; g++) {
                // stream X: rr = 2g, stream Y: rr = 2g+1
                const int qX = lane + 64 * g;
                const int qY = qX + 32;

                const int yX = qX >> 3, xX = (qX & 7) * 2;
                const int yY = qY >> 3, xY = (qY & 7) * 2;
                const float* rpX = sxw + yX * XSTRIDE + xX;
                const float* rpY = sxw + yY * XSTRIDE + xY;

                u64 cX = bias2, cY = bias2;
                #pragma unroll
                for (int r = 0; r < 3; r++) {
                    const float* rqX = rpX + r * XSTRIDE;
                    const float* rqY = rpY + r * XSTRIDE;
                    u64 t0X = *(const u64*)(rqX);
                    u64 t1X = *(const u64*)(rqX + 2);
                    u64 t0Y = *(const u64*)(rqY);
                    u64 t1Y = *(const u64*)(rqY + 2);
                    float t0lX, t0hX, t1lX, t1hX;
                    float t0lY, t0hY, t1lY, t1hY;
                    unpack2(t0X, t0lX, t0hX);
                    unpack2(t1X, t1lX, t1hX);
                    unpack2(t0Y, t0lY, t0hY);
                    unpack2(t1Y, t1lY, t1hY);
                    cX = fma2(wp[3 * r + 0], t0X, cX);
                    cY = fma2(wp[3 * r + 0], t0Y, cY);
                    cX = fma2(wp[3 * r + 1], pack2(t0hX, t1lX), cX);
                    cY = fma2(wp[3 * r + 1], pack2(t0hY, t1lY), cY);
                    cX = fma2(wp[3 * r + 2], t1X, cX);
                    cY = fma2(wp[3 * r + 2], t1Y, cY);
                }

                const int ibX = ch * 256 + qX * 2;
                const int ibY = ch * 256 + qY * 2;
                const u64 w0pX = *(const u64*)&sw0[ibX];
                const u64 w1pX = *(const u64*)&sw1[ibX];
                const u64 w0pY = *(const u64*)&sw0[ibY];
                const u64 w1pY = *(const u64*)&sw1[ibY];

                u64 mX = 0ull, sX = 0ull;
                u64 mY = 0ull, sY = 0ull;
                #pragma unroll
                for (int t = 0; t < NSTEP; t++) {
                    mX = fma2(BETA2, mX, cX);
                    mY = fma2(BETA2, mY, cY);
                    mX = fma2(sX, NEG1_2, mX);
                    mY = fma2(sY, NEG1_2, mY);
                    float maX, mbX, maY, mbY;
                    unpack2(mX, maX, mbX);
                    unpack2(mY, maY, mbY);
                    sX = pack2(setgt1(maX), setgt1(mbX));
                    sY = pack2(setgt1(maY), setgt1(mbY));
                    // accumulate X before Y: per-t order rr0,rr1,rr2,rr3,
                    // identical to the single-stream kernel
                    A0[t] = fma2(sX, w0pX, A0[t]);
                    A0[t] = fma2(sY, w0pY, A0[t]);
                    A1[t] = fma2(sX, w1pX, A1[t]);
                    A1[t] = fma2(sY, w1pY, A1[t]);
                }
            }
        }

        float r0[NSTEP], r1[NSTEP];
        #pragma unroll
        for (int t = 0; t < NSTEP; t++) {
            float a, c;
            unpack2(A0[t], a, c); r0[t] = a + c;
            unpack2(A1[t], a, c); r1[t] = a + c;
        }
        #pragma unroll
        for (int off = 16; off > 0; off >>= 1) {
            #pragma unroll
            for (int t = 0; t < NSTEP; t++) {
                r0[t] += __shfl_down_sync(0xffffffffu, r0[t], off);
                r1[t] += __shfl_down_sync(0xffffffffu, r1[t], off);
            }
        }

        if (lane == 0) {
            const float fb0 = fcb[0], fb1 = fcb[1];
            float m20 = 0.f, m21 = 0.f, s20 = 0.f, s21 = 0.f, o0 = 0.f, o1 = 0.f;
            #pragma unroll
            for (int t = 0; t < NSTEP; t++) {
                float c0 = r0[t] + fb0;
                float c1 = r1[t] + fb1;
                m20 = fmaf(0.9f, m20, c0) - s20;
                m21 = fmaf(0.9f, m21, c1) - s21;
                s20 = (m20 > 1.0f) ? 1.0f : 0.0f;
                s21 = (m21 > 1.0f) ? 1.0f : 0.0f;
                o0 += s20;
                o1 += s21;
            }
            out[b * 2 + 0] = o0;
            out[b * 2 + 1] = o1;
        }
    }
}

extern "C" void kernel_launch(void* const* d_in, const int* in_sizes, int n_in,
                              void* d_out, int out_size) {
    const float* x  = (const float*)d_in[0];
    const float* cw = (const float*)d_in[1];
    const float* cb = (const float*)d_in[2];
    const float* fw = (const float*)d_in[3];
    const float* fb = (const float*)d_in[4];
    float* out = (float*)d_out;

    const int nB = in_sizes[0] / 256;
    const int blocks = (nB + WARPS - 1) / WARPS;
    snn_kernel<<<blocks, THREADS>>>(x, cw, cb, fw, fb, out, nB);
}

// round 4
// speedup vs baseline: 1.0633x; 1.0633x over previous
#include <cuda_runtime.h>

#define WARPS 8
#define THREADS 256
#define NSTEP 10
#define XSTRIDE 48   // floats per padded row; 48 % 32 == 16 -> conflict-free LDS.64

typedef unsigned long long u64;

__device__ __forceinline__ float setgt1(float a) {
    float r;
    asm("set.gt.f32.f32 %0, %1, %2;" : "=f"(r) : "f"(a), "f"(1.0f));
    return r;
}
__device__ __forceinline__ u64 fma2(u64 a, u64 b, u64 c) {
    u64 d;
    asm("fma.rn.f32x2 %0, %1, %2, %3;" : "=l"(d) : "l"(a), "l"(b), "l"(c));
    return d;
}
__device__ __forceinline__ u64 pack2(float lo, float hi) {
    u64 d;
    asm("mov.b64 %0, {%1, %2};" : "=l"(d) : "f"(lo), "f"(hi));
    return d;
}
__device__ __forceinline__ void unpack2(u64 v, float& lo, float& hi) {
    asm("mov.b64 {%0, %1}, %2;" : "=f"(lo), "=f"(hi) : "l"(v));
}

// One warp per sample, 32 element-pairs per lane. Layer-1 membrane packed
// (f32x2, one pair per register). The 10 per-step FC partial sums accumulate
// CHANNEL-packed: A[t] = (sum s*w0, sum s*w1), fed by per-element spike
// broadcasts against interleaved weight pairs -- 10 u64 accumulators (20
// regs) instead of 20 (40 regs), buying 4 CTAs/SM residency.
__global__ void __launch_bounds__(THREADS, 4)
snn_kernel(const float* __restrict__ x, const float* __restrict__ convw,
           const float* __restrict__ convb, const float* __restrict__ fcw,
           const float* __restrict__ fcb, float* __restrict__ out, int nB)
{
    __shared__ __align__(16) float sx[WARPS][18 * XSTRIDE];
    __shared__ __align__(16) float sw01[4096];   // interleaved (w0_i, w1_i)
    __shared__ float scw[72];
    __shared__ float scb[8];

    const int tid  = threadIdx.x;
    const int warp = tid >> 5;
    const int lane = tid & 31;
    const long long b = (long long)blockIdx.x * WARPS + warp;

    for (int i = tid; i < 2048; i += THREADS) {
        sw01[2 * i]     = fcw[i];
        sw01[2 * i + 1] = fcw[2048 + i];
    }
    if (tid < 72) scw[tid] = convw[tid];
    if (tid < 8)  scb[tid] = convb[tid];

    float* sxw = sx[warp];
    #pragma unroll
    for (int i = lane; i < 18 * XSTRIDE; i += 32) sxw[i] = 0.0f;
    __syncwarp();

    if (b < nB) {
        const float4* xb = (const float4*)(x + b * 256);
        #pragma unroll
        for (int i = lane; i < 64; i += 32) {
            float4 v = xb[i];
            int p = i * 4;
            int y = p >> 4, xx = p & 15;
            float* d = &sxw[(y + 1) * XSTRIDE + xx + 1];
            d[0] = v.x; d[1] = v.y; d[2] = v.z; d[3] = v.w;
        }
    }
    __syncthreads();

    if (b < nB) {
        u64 A[NSTEP];
        #pragma unroll
        for (int t = 0; t < NSTEP; t++) A[t] = 0ull;

        const u64 BETA2  = 0x3F6666663F666666ull; // (0.9f, 0.9f)
        const u64 NEG1_2 = 0xBF800000BF800000ull; // (-1.f, -1.f)

        #pragma unroll 1
        for (int ch = 0; ch < 8; ch++) {
            float w[9];
            #pragma unroll
            for (int k = 0; k < 9; k++) w[k] = scw[ch * 9 + k];
            const float cbias = scb[ch];

            #pragma unroll 1
            for (int rr = 0; rr < 4; rr++) {
                const int q  = lane + 32 * rr;   // pair index in channel
                const int y  = q >> 3;
                const int x0 = (q & 7) * 2;
                const float* rp = sxw + y * XSTRIDE + x0;
                float2 t00 = *(const float2*)(rp);
                float2 t01 = *(const float2*)(rp + 2);
                float2 t10 = *(const float2*)(rp + XSTRIDE);
                float2 t11 = *(const float2*)(rp + XSTRIDE + 2);
                float2 t20 = *(const float2*)(rp + 2 * XSTRIDE);
                float2 t21 = *(const float2*)(rp + 2 * XSTRIDE + 2);

                // scalar conv, identical op order to the R1 kernel
                float ca = cbias, cb = cbias;
                ca = fmaf(w[0], t00.x, ca);  cb = fmaf(w[0], t00.y, cb);
                ca = fmaf(w[1], t00.y, ca);  cb = fmaf(w[1], t01.x, cb);
                ca = fmaf(w[2], t01.x, ca);  cb = fmaf(w[2], t01.y, cb);
                ca = fmaf(w[3], t10.x, ca);  cb = fmaf(w[3], t10.y, cb);
                ca = fmaf(w[4], t10.y, ca);  cb = fmaf(w[4], t11.x, cb);
                ca = fmaf(w[5], t11.x, ca);  cb = fmaf(w[5], t11.y, cb);
                ca = fmaf(w[6], t20.x, ca);  cb = fmaf(w[6], t20.y, cb);
                ca = fmaf(w[7], t20.y, ca);  cb = fmaf(w[7], t21.x, cb);
                ca = fmaf(w[8], t21.x, ca);  cb = fmaf(w[8], t21.y, cb);

                const int ib = ch * 256 + q * 2;  // flat element idx (even)
                // interleaved weight pairs for elements ib, ib+1: one LDS.128
                const float4 wv = *(const float4*)&sw01[2 * ib];
                const u64 wlo = pack2(wv.x, wv.y);   // (w0_ib,   w1_ib)
                const u64 whi = pack2(wv.z, wv.w);   // (w0_ib+1, w1_ib+1)
                const u64 c2  = pack2(ca, cb);

                u64 m2 = 0ull, s2 = 0ull;
                #pragma unroll
                for (int t = 0; t < NSTEP; t++) {
                    m2 = fma2(BETA2, m2, c2);     // beta*m + c
                    m2 = fma2(s2, NEG1_2, m2);    // - reset (prev spike)
                    float ma, mb;
                    unpack2(m2, ma, mb);
                    float sa = setgt1(ma);
                    float sb = setgt1(mb);
                    s2 = pack2(sa, sb);
                    A[t] = fma2(pack2(sa, sa), wlo, A[t]);
                    A[t] = fma2(pack2(sb, sb), whi, A[t]);
                }
            }
        }

        // warp-reduce the 10 packed (out0, out1) partial sums
        float r0[NSTEP], r1[NSTEP];
        #pragma unroll
        for (int t = 0; t < NSTEP; t++) unpack2(A[t], r0[t], r1[t]);
        #pragma unroll
        for (int off = 16; off > 0; off >>= 1) {
            #pragma unroll
            for (int t = 0; t < NSTEP; t++) {
                r0[t] += __shfl_down_sync(0xffffffffu, r0[t], off);
                r1[t] += __shfl_down_sync(0xffffffffu, r1[t], off);
            }
        }

        if (lane == 0) {
            const float fb0 = fcb[0], fb1 = fcb[1];
            float m20 = 0.f, m21 = 0.f, s20 = 0.f, s21 = 0.f, o0 = 0.f, o1 = 0.f;
            #pragma unroll
            for (int t = 0; t < NSTEP; t++) {
                float c0 = r0[t] + fb0;
                float c1 = r1[t] + fb1;
                m20 = fmaf(0.9f, m20, c0) - s20;
                m21 = fmaf(0.9f, m21, c1) - s21;
                s20 = (m20 > 1.0f) ? 1.0f : 0.0f;
                s21 = (m21 > 1.0f) ? 1.0f : 0.0f;
                o0 += s20;
                o1 += s21;
            }
            out[b * 2 + 0] = o0;
            out[b * 2 + 1] = o1;
        }
    }
}

extern "C" void kernel_launch(void* const* d_in, const int* in_sizes, int n_in,
                              void* d_out, int out_size) {
    const float* x  = (const float*)d_in[0];
    const float* cw = (const float*)d_in[1];
    const float* cb = (const float*)d_in[2];
    const float* fw = (const float*)d_in[3];
    const float* fb = (const float*)d_in[4];
    float* out = (float*)d_out;

    const int nB = in_sizes[0] / 256;
    const int blocks = (nB + WARPS - 1) / WARPS;
    snn_kernel<<<blocks, THREADS>>>(x, cw, cb, fw, fb, out, nB);
}

// round 5
// speedup vs baseline: 1.0843x; 1.0197x over previous
#include <cuda_runtime.h>

#define WARPS 8
#define THREADS 256
#define NSTEP 10
#define XSTRIDE 48   // floats per padded row; 48 % 32 == 16 -> conflict-free LDS.64

typedef unsigned long long u64;

__device__ __forceinline__ float setgt1(float a) {
    float r;
    asm("set.gt.f32.f32 %0, %1, %2;" : "=f"(r) : "f"(a), "f"(1.0f));
    return r;
}
__device__ __forceinline__ u64 fma2(u64 a, u64 b, u64 c) {
    u64 d;
    asm("fma.rn.f32x2 %0, %1, %2, %3;" : "=l"(d) : "l"(a), "l"(b), "l"(c));
    return d;
}
__device__ __forceinline__ u64 pack2(float lo, float hi) {
    u64 d;
    asm("mov.b64 %0, {%1, %2};" : "=l"(d) : "f"(lo), "f"(hi));
    return d;
}
__device__ __forceinline__ void unpack2(u64 v, float& lo, float& hi) {
    asm("mov.b64 {%0, %1}, %2;" : "=f"(lo), "=f"(hi) : "l"(v));
}

// One warp per sample, 32 element-pairs per lane. LOOP ORDER rr-outer /
// ch-inner: the 6 conv-tap LDS depend only on the spatial pair index q, so
// they are loaded once per rr (4x per lane) and reused across all 8
// channels, instead of reloaded 32x. Conv weights+bias come from a padded
// [8][12] float4 layout via 3 broadcast LDS.128 per channel. Membrane packed
// f32x2; 10 channel-packed (out0,out1) accumulators.
__global__ void __launch_bounds__(THREADS, 4)
snn_kernel(const float* __restrict__ x, const float* __restrict__ convw,
           const float* __restrict__ convb, const float* __restrict__ fcw,
           const float* __restrict__ fcb, float* __restrict__ out, int nB)
{
    __shared__ __align__(16) float sx[WARPS][18 * XSTRIDE];
    __shared__ __align__(16) float sw01[4096];    // interleaved (w0_i, w1_i)
    __shared__ __align__(16) float scw4[8 * 12];  // per ch: w0..w8, bias, pad, pad

    const int tid  = threadIdx.x;
    const int warp = tid >> 5;
    const int lane = tid & 31;
    const long long b = (long long)blockIdx.x * WARPS + warp;

    for (int i = tid; i < 2048; i += THREADS) {
        sw01[2 * i]     = fcw[i];
        sw01[2 * i + 1] = fcw[2048 + i];
    }
    if (tid < 96) {
        int ch = tid / 12, k = tid % 12;
        float v = 0.0f;
        if (k < 9)       v = convw[ch * 9 + k];
        else if (k == 9) v = convb[ch];
        scw4[tid] = v;
    }

    float* sxw = sx[warp];
    #pragma unroll
    for (int i = lane; i < 18 * XSTRIDE; i += 32) sxw[i] = 0.0f;
    __syncwarp();

    if (b < nB) {
        const float4* xb = (const float4*)(x + b * 256);
        #pragma unroll
        for (int i = lane; i < 64; i += 32) {
            float4 v = xb[i];
            int p = i * 4;
            int y = p >> 4, xx = p & 15;
            float* d = &sxw[(y + 1) * XSTRIDE + xx + 1];
            d[0] = v.x; d[1] = v.y; d[2] = v.z; d[3] = v.w;
        }
    }
    __syncthreads();

    if (b < nB) {
        u64 A[NSTEP];
        #pragma unroll
        for (int t = 0; t < NSTEP; t++) A[t] = 0ull;

        const u64 BETA2  = 0x3F6666663F666666ull; // (0.9f, 0.9f)
        const u64 NEG1_2 = 0xBF800000BF800000ull; // (-1.f, -1.f)

        #pragma unroll 1
        for (int rr = 0; rr < 4; rr++) {
            const int q  = lane + 32 * rr;   // pair index in channel
            const int y  = q >> 3;
            const int x0 = (q & 7) * 2;
            const float* rp = sxw + y * XSTRIDE + x0;
            // taps live in registers across the whole channel loop
            const float2 t00 = *(const float2*)(rp);
            const float2 t01 = *(const float2*)(rp + 2);
            const float2 t10 = *(const float2*)(rp + XSTRIDE);
            const float2 t11 = *(const float2*)(rp + XSTRIDE + 2);
            const float2 t20 = *(const float2*)(rp + 2 * XSTRIDE);
            const float2 t21 = *(const float2*)(rp + 2 * XSTRIDE + 2);

            const int qb = q * 2;            // flat even element within channel

            #pragma unroll 1
            for (int ch = 0; ch < 8; ch++) {
                const float4* cw4 = (const float4*)&scw4[ch * 12];
                const float4 wA = cw4[0];   // w0 w1 w2 w3
                const float4 wB = cw4[1];   // w4 w5 w6 w7
                const float4 wC = cw4[2];   // w8 bias - -

                // scalar conv, op order identical to prior rounds
                float ca = wC.y, cb = wC.y;
                ca = fmaf(wA.x, t00.x, ca);  cb = fmaf(wA.x, t00.y, cb);
                ca = fmaf(wA.y, t00.y, ca);  cb = fmaf(wA.y, t01.x, cb);
                ca = fmaf(wA.z, t01.x, ca);  cb = fmaf(wA.z, t01.y, cb);
                ca = fmaf(wA.w, t10.x, ca);  cb = fmaf(wA.w, t10.y, cb);
                ca = fmaf(wB.x, t10.y, ca);  cb = fmaf(wB.x, t11.x, cb);
                ca = fmaf(wB.y, t11.x, ca);  cb = fmaf(wB.y, t11.y, cb);
                ca = fmaf(wB.z, t20.x, ca);  cb = fmaf(wB.z, t20.y, cb);
                ca = fmaf(wB.w, t20.y, ca);  cb = fmaf(wB.w, t21.x, cb);
                ca = fmaf(wC.x, t21.x, ca);  cb = fmaf(wC.x, t21.y, cb);

                const int ib = ch * 256 + qb;
                const float4 wv = *(const float4*)&sw01[2 * ib];
                const u64 wlo = pack2(wv.x, wv.y);   // (w0_ib,   w1_ib)
                const u64 whi = pack2(wv.z, wv.w);   // (w0_ib+1, w1_ib+1)
                const u64 c2  = pack2(ca, cb);

                u64 m2 = 0ull, s2 = 0ull;
                #pragma unroll
                for (int t = 0; t < NSTEP; t++) {
                    m2 = fma2(BETA2, m2, c2);     // beta*m + c
                    m2 = fma2(s2, NEG1_2, m2);    // - reset (prev spike)
                    float ma, mb;
                    unpack2(m2, ma, mb);
                    float sa = setgt1(ma);
                    float sb = setgt1(mb);
                    s2 = pack2(sa, sb);
                    A[t] = fma2(pack2(sa, sa), wlo, A[t]);
                    A[t] = fma2(pack2(sb, sb), whi, A[t]);
                }
            }
        }

        // warp-reduce the 10 packed (out0, out1) partial sums
        float r0[NSTEP], r1[NSTEP];
        #pragma unroll
        for (int t = 0; t < NSTEP; t++) unpack2(A[t], r0[t], r1[t]);
        #pragma unroll
        for (int off = 16; off > 0; off >>= 1) {
            #pragma unroll
            for (int t = 0; t < NSTEP; t++) {
                r0[t] += __shfl_down_sync(0xffffffffu, r0[t], off);
                r1[t] += __shfl_down_sync(0xffffffffu, r1[t], off);
            }
        }

        if (lane == 0) {
            const float fb0 = fcb[0], fb1 = fcb[1];
            float m20 = 0.f, m21 = 0.f, s20 = 0.f, s21 = 0.f, o0 = 0.f, o1 = 0.f;
            #pragma unroll
            for (int t = 0; t < NSTEP; t++) {
                float c0 = r0[t] + fb0;
                float c1 = r1[t] + fb1;
                m20 = fmaf(0.9f, m20, c0) - s20;
                m21 = fmaf(0.9f, m21, c1) - s21;
                s20 = (m20 > 1.0f) ? 1.0f : 0.0f;
                s21 = (m21 > 1.0f) ? 1.0f : 0.0f;
                o0 += s20;
                o1 += s21;
            }
            out[b * 2 + 0] = o0;
            out[b * 2 + 1] = o1;
        }
    }
}

extern "C" void kernel_launch(void* const* d_in, const int* in_sizes, int n_in,
                              void* d_out, int out_size) {
    const float* x  = (const float*)d_in[0];
    const float* cw = (const float*)d_in[1];
    const float* cb = (const float*)d_in[2];
    const float* fw = (const float*)d_in[3];
    const float* fb = (const float*)d_in[4];
    float* out = (float*)d_out;

    const int nB = in_sizes[0] / 256;
    const int blocks = (nB + WARPS - 1) / WARPS;
    snn_kernel<<<blocks, THREADS>>>(x, cw, cb, fw, fb, out, nB);
}